// round 7
// baseline (speedup 1.0000x reference)
#include <cuda_runtime.h>
#include <math_constants.h>
#include <cstdint>

#define NROWS 16384
#define DIM   256
#define KCB   8192
#define MT    64                 /* rows per CTA           */
#define MTILES (NROWS / MT)      /* 256 CTAs               */
#define NTILES (KCB / 128)       /* 64 code tiles          */
#define NHALF  (2 * NTILES)      /* 128 k128xn128 halves   */
#define NPART (NROWS / 8)

/* GEMM smem layout (dynamic) */
#define SA_OFF  0                /* A fp8: 64 rows x 256B = 16KB        */
#define SB_OFF  16384            /* 2 x 16KB B half double buffer       */
#define SCN_OFF 49152            /* 2 x 512B codenorm tiles             */
#define GEMM_SMEM 50176

/* ------------- device globals (no allocs allowed) ------------- */
__device__ unsigned char g_zt[MTILES * 16384];       /* 4MB pre-swizzled A fp8  */
__device__ unsigned char g_cbt[NTILES * 32768];      /* 2MB pre-swizzled B fp8  */
__device__ float g_codenorm[KCB];
__device__ int   g_cand[NROWS * 8];
__device__ float g_losspart[NPART];

/* ------------- helpers ------------- */
__device__ __forceinline__ unsigned smem_u32(const void* p) {
    unsigned a;
    asm("{ .reg .u64 t; cvta.to.shared.u64 t, %1; cvt.u32.u64 %0, t; }" : "=r"(a) : "l"(p));
    return a;
}
__device__ __forceinline__ void cp_async16(unsigned dst, const void* src) {
    asm volatile("cp.async.cg.shared.global [%0], [%1], 16;" :: "r"(dst), "l"(src) : "memory");
}
__device__ __forceinline__ void ldsm_x4(unsigned* r, unsigned addr) {
    asm volatile("ldmatrix.sync.aligned.m8n8.x4.shared.b16 {%0,%1,%2,%3}, [%4];"
                 : "=r"(r[0]), "=r"(r[1]), "=r"(r[2]), "=r"(r[3]) : "r"(addr));
}
__device__ __forceinline__ void mma16832(float (&c)[4], const unsigned* a, unsigned b0, unsigned b1) {
    asm volatile("mma.sync.aligned.m16n8k32.row.col.f32.e4m3.e4m3.f32 "
                 "{%0,%1,%2,%3}, {%4,%5,%6,%7}, {%8,%9}, {%0,%1,%2,%3};"
                 : "+f"(c[0]), "+f"(c[1]), "+f"(c[2]), "+f"(c[3])
                 : "r"(a[0]), "r"(a[1]), "r"(a[2]), "r"(a[3]), "r"(b0), "r"(b1));
}
/* pack 2 floats into 2 e4m3 bytes (same convention for A and B -> order cancels in dot) */
__device__ __forceinline__ unsigned short cvt2_e4m3(float lo, float hi) {
    unsigned short r;
    asm("cvt.rn.satfinite.e4m3x2.f32 %0, %1, %2;" : "=h"(r) : "f"(hi), "f"(lo));
    return r;
}
__device__ __forceinline__ void top3_update(float& v1, int& i1, float& v2, int& i2,
                                            float& v3, int& i3, float d, int c) {
    if (d < v3) {
        if (d < v2) {
            v3 = v2; i3 = i2;
            if (d < v1) { v2 = v1; i2 = i1; v1 = d; i1 = c; }
            else        { v2 = d;  i2 = c; }
        } else { v3 = d; i3 = c; }
    }
}
__device__ __forceinline__ void ins8(float (&cv)[8], int (&ci)[8], float v, int i) {
#pragma unroll
    for (int j = 0; j < 8; j++) {
        bool lt = (v < cv[j]) || (v == cv[j] && i < ci[j]);
        float tv = lt ? cv[j] : v; int ti = lt ? ci[j] : i;
        if (lt) { cv[j] = v; ci[j] = i; }
        v = tv; i = ti;
    }
}

/* ---------- preprocess: z -> swizzled fp8 A tiles (64 rows x 256B) ---------- */
__global__ void split_z_kernel(const float* __restrict__ z) {
    const int id = blockIdx.x * 256 + threadIdx.x;   /* 0..262143 */
    const int row = id >> 4, kb = id & 15;           /* 16B block along k */
    const float4* s = (const float4*)(z + (size_t)row * DIM + kb * 16);
    float4 f[4] = {__ldg(s), __ldg(s + 1), __ldg(s + 2), __ldg(s + 3)};
    const float* v = (const float*)f;
    unsigned short h[8];
#pragma unroll
    for (int e = 0; e < 8; e++) h[e] = cvt2_e4m3(v[2 * e], v[2 * e + 1]);
    size_t dst = (size_t)(row >> 6) * 16384 + (size_t)(row & 63) * 256 + ((kb ^ (row & 7)) << 4);
    *(uint4*)(g_zt + dst) = *(uint4*)h;
}

/* ---------- preprocess: codebook -> swizzled fp8 B tiles (128n x 128B per half) ---------- */
__global__ void split_cb_kernel(const float* __restrict__ cb) {
    const int id = blockIdx.x * 256 + threadIdx.x;   /* 0..131071 */
    const int n = id >> 4, kb16 = id & 15;
    const float4* s = (const float4*)(cb + (size_t)n * DIM + kb16 * 16);
    float4 f[4] = {__ldg(s), __ldg(s + 1), __ldg(s + 2), __ldg(s + 3)};
    const float* v = (const float*)f;
    unsigned short h[8];
#pragma unroll
    for (int e = 0; e < 8; e++) h[e] = cvt2_e4m3(v[2 * e], v[2 * e + 1]);
    const int kb = kb16 & 7, hh = kb16 >> 3;
    size_t dst = (size_t)(n >> 7) * 32768 + (size_t)hh * 16384
               + (size_t)(n & 127) * 128 + ((kb ^ (n & 7)) << 4);
    *(uint4*)(g_cbt + dst) = *(uint4*)h;
}

/* ---------- exact fp32 codebook norms ---------- */
__global__ void codenorm_kernel(const float* __restrict__ cb) {
    int warp = threadIdx.x >> 5, lane = threadIdx.x & 31;
    int row = blockIdx.x * 8 + warp;
    const float4* c4 = (const float4*)(cb + (size_t)row * DIM);
    float s = 0.f;
#pragma unroll
    for (int l = 0; l < 2; l++) {
        float4 v = c4[lane + 32 * l];
        s += v.x * v.x + v.y * v.y + v.z * v.z + v.w * v.w;
    }
#pragma unroll
    for (int o = 16; o > 0; o >>= 1) s += __shfl_down_sync(0xffffffffu, s, o);
    if (lane == 0) g_codenorm[row] = s;
}

/* ---------- B-half producer: 16KB into buffer (s&1), one commit group ---------- */
__device__ __forceinline__ void issue_half(unsigned smb, int s, int tid) {
    const unsigned char* src = g_cbt + (size_t)s * 16384 + tid * 16;
    unsigned dst = smb + SB_OFF + (s & 1) * 16384 + tid * 16;
#pragma unroll
    for (int i = 0; i < 4; i++) cp_async16(dst + i * 4096, src + (size_t)i * 4096);
    if ((s & 1) == 0 && tid < 32)
        cp_async16(smb + SCN_OFF + ((s >> 1) & 1) * 512 + tid * 16,
                   (const unsigned char*)g_codenorm + (size_t)(s >> 1) * 512 + tid * 16);
    asm volatile("cp.async.commit_group;" ::: "memory");
}

/* ---------- compute one k128 half: 4 k32-steps, buf = H ---------- */
template<int H>
__device__ __forceinline__ void compute_half(float (&acc)[2][4][4], unsigned smb,
                                             int wm, int wn, int lane) {
    const int lm = lane & 15;
    const int sel = lane >> 4;
    const int mlo = wm * 32 + lm, mhi = mlo + 16;
    const unsigned aL = smb + SA_OFF + mlo * 256;
    const unsigned aH = smb + SA_OFF + mhi * 256;
    const int xlo = mlo & 7, xhi = mhi & 7;
    const int nn = wn * 32 + lm;
    const int xb = nn & 7;                       /* (nn+16)&7 == nn&7 */
    const unsigned b0a = smb + SB_OFF + H * 16384 + nn * 128;
    const unsigned b1a = b0a + 16 * 128;
#pragma unroll
    for (int s = 0; s < 4; s++) {
        const int kA = H * 8 + 2 * s + sel;      /* 16B block in A row (0..15) */
        const int kB = 2 * s + sel;              /* 16B block in B row (0..7)  */
        unsigned a0[4], a1[4], b0[4], b1[4];
        ldsm_x4(a0, aL + ((kA ^ xlo) << 4));
        ldsm_x4(a1, aH + ((kA ^ xhi) << 4));
        ldsm_x4(b0, b0a + ((kB ^ xb) << 4));
        ldsm_x4(b1, b1a + ((kB ^ xb) << 4));
        /* b pairing: (r0,r2) = n-block lo (k0-15,k16-31), (r1,r3) = n-block hi */
        mma16832(acc[0][0], a0, b0[0], b0[2]);
        mma16832(acc[0][1], a0, b0[1], b0[3]);
        mma16832(acc[0][2], a0, b1[0], b1[2]);
        mma16832(acc[0][3], a0, b1[1], b1[3]);
        mma16832(acc[1][0], a1, b0[0], b0[2]);
        mma16832(acc[1][1], a1, b0[1], b0[3]);
        mma16832(acc[1][2], a1, b1[0], b1[2]);
        mma16832(acc[1][3], a1, b1[1], b1[3]);
    }
}

/* ---------- K1: fp8 tensor GEMM + fused top-3/thread argmin ---------- */
__global__ void __launch_bounds__(256, 2) vq_mma_kernel() {
    extern __shared__ __align__(128) unsigned char smem[];
    const unsigned smb = smem_u32(smem);
    const int tid = threadIdx.x;
    const int lane = tid & 31;
    const int w = tid >> 5;
    const int wm = w >> 2, wn = w & 3;
    const int mtile = blockIdx.x;

    { /* prologue group: resident A (16KB) + half 0 + cn tile 0 */
        const unsigned char* src = g_zt + (size_t)mtile * 16384 + tid * 16;
        unsigned dst = smb + SA_OFF + tid * 16;
#pragma unroll
        for (int i = 0; i < 4; i++) cp_async16(dst + i * 4096, src + (size_t)i * 4096);
        issue_half(smb, 0, tid);   /* commits A + half0 + cn0 as one group */
    }

    float acc[2][4][4];
#pragma unroll
    for (int i = 0; i < 2; i++)
#pragma unroll
        for (int j = 0; j < 4; j++)
#pragma unroll
            for (int r = 0; r < 4; r++) acc[i][j][r] = 0.f;
    float tv1[4], tv2[4], tv3[4];
    int ti1[4], ti2[4], ti3[4];
#pragma unroll
    for (int sl = 0; sl < 4; sl++) {
        tv1[sl] = CUDART_INF_F; tv2[sl] = CUDART_INF_F; tv3[sl] = CUDART_INF_F;
        ti1[sl] = 0x7fffffff; ti2[sl] = 0x7fffffff; ti3[sl] = 0x7fffffff;
    }

    const int colb = wn * 32 + 2 * (lane & 3);
    for (int ii = 0; ii < NTILES; ii++) {
        /* ---- half 0 of tile ii (k 0-127) ---- */
        asm volatile("cp.async.wait_group 0;" ::: "memory");
        __syncthreads();
        issue_half(smb, 2 * ii + 1, tid);
        compute_half<0>(acc, smb, wm, wn, lane);
        /* ---- half 1 of tile ii (k 128-255) ---- */
        asm volatile("cp.async.wait_group 0;" ::: "memory");
        __syncthreads();
        if (2 * ii + 2 < NHALF) issue_half(smb, 2 * ii + 2, tid);
        compute_half<1>(acc, smb, wm, wn, lane);
        { /* epilogue: dist + top-3, zero acc */
            const float* cnp = (const float*)(smem + SCN_OFF + (ii & 1) * 512);
#pragma unroll
            for (int ni = 0; ni < 4; ni++) {
                float cn0 = cnp[colb + ni * 8];
                float cn1 = cnp[colb + ni * 8 + 1];
                int c0 = ii * 128 + colb + ni * 8;
#pragma unroll
                for (int mi = 0; mi < 2; mi++) {
#pragma unroll
                    for (int h = 0; h < 2; h++) {
                        int sl = mi * 2 + h;
                        float d0 = fmaf(-2.f, acc[mi][ni][h * 2],     cn0);
                        float d1 = fmaf(-2.f, acc[mi][ni][h * 2 + 1], cn1);
                        top3_update(tv1[sl], ti1[sl], tv2[sl], ti2[sl], tv3[sl], ti3[sl], d0, c0);
                        top3_update(tv1[sl], ti1[sl], tv2[sl], ti2[sl], tv3[sl], ti3[sl], d1, c0 + 1);
                        acc[mi][ni][h * 2] = 0.f;
                        acc[mi][ni][h * 2 + 1] = 0.f;
                    }
                }
            }
        }
    }

    /* dump 48 per-row candidates, then per-row top-8 merge */
    __syncthreads();
    float2* red = (float2*)(smem + SB_OFF);    /* 64 rows x 48 entries x 8B = 24KB */
    const int t = wn * 4 + (lane & 3);
#pragma unroll
    for (int sl = 0; sl < 4; sl++) {
        int row = wm * 32 + (sl >> 1) * 16 + (sl & 1) * 8 + (lane >> 2);
        float2* p = red + row * 48 + t * 3;
        p[0] = make_float2(tv1[sl], __int_as_float(ti1[sl]));
        p[1] = make_float2(tv2[sl], __int_as_float(ti2[sl]));
        p[2] = make_float2(tv3[sl], __int_as_float(ti3[sl]));
    }
    __syncthreads();
    if (tid < 64) {
        float cv[8]; int ci[8];
#pragma unroll
        for (int j = 0; j < 8; j++) { cv[j] = CUDART_INF_F; ci[j] = 0x7fffffff; }
#pragma unroll 4
        for (int e = 0; e < 48; e++) {
            float2 f = red[tid * 48 + e];
            ins8(cv, ci, f.x, __float_as_int(f.y));
        }
        int* dst = g_cand + (size_t)(mtile * MT + tid) * 8;
        *(int4*)dst       = make_int4(ci[0], ci[1], ci[2], ci[3]);
        *(int4*)(dst + 4) = make_int4(ci[4], ci[5], ci[6], ci[7]);
    }
}

/* ---------- K2: exact fp32 rescore of top-8 + gather + loss partials ---------- */
__global__ void rescore_gather_kernel(const float* __restrict__ z,
                                      const float* __restrict__ cb,
                                      float* __restrict__ out) {
    const int lane = threadIdx.x & 31, warp = threadIdx.x >> 5;
    const int row = blockIdx.x * 8 + warp;
    __shared__ float wsum[8];

    const int4 c0 = *(const int4*)(g_cand + (size_t)row * 8);
    const int4 c1 = *(const int4*)(g_cand + (size_t)row * 8 + 4);
    const int cand[8] = {c0.x, c0.y, c0.z, c0.w, c1.x, c1.y, c1.z, c1.w};
    const float4* z4 = (const float4*)(z + (size_t)row * DIM);
    const float4 a0 = z4[lane], a1 = z4[lane + 32];
    float d[8];
#pragma unroll
    for (int q = 0; q < 8; q++) {
        const float4* e4 = (const float4*)(cb + (size_t)cand[q] * DIM);
        float4 b0 = e4[lane], b1 = e4[lane + 32];
        d[q] = a0.x * b0.x + a0.y * b0.y + a0.z * b0.z + a0.w * b0.w
             + a1.x * b1.x + a1.y * b1.y + a1.z * b1.z + a1.w * b1.w;
    }
#pragma unroll
    for (int o = 16; o > 0; o >>= 1)
#pragma unroll
        for (int q = 0; q < 8; q++) d[q] += __shfl_xor_sync(0xffffffffu, d[q], o);

    float bv = CUDART_INF_F; int bi = 0x7fffffff;
#pragma unroll
    for (int q = 0; q < 8; q++) {
        float dist = fmaf(-2.f, d[q], __ldg(&g_codenorm[cand[q]]));
        if (dist < bv || (dist == bv && cand[q] < bi)) { bv = dist; bi = cand[q]; }
    }

    const float4* e4 = (const float4*)(cb + (size_t)bi * DIM);
    float* out_ze = out + (size_t)row * DIM;
    float* out_zq = out + (size_t)NROWS * DIM + 1 + (size_t)row * DIM;
    float s = 0.f;
#pragma unroll
    for (int l = 0; l < 2; l++) {
        int f = lane + 32 * l;
        float4 ze = (l == 0) ? a0 : a1;
        float4 zq = e4[f];
        *(float4*)(out_ze + f * 4) = ze;
        out_zq[f * 4 + 0] = zq.x; out_zq[f * 4 + 1] = zq.y;
        out_zq[f * 4 + 2] = zq.z; out_zq[f * 4 + 3] = zq.w;
        float dx = zq.x - ze.x, dy = zq.y - ze.y, dz = zq.z - ze.z, dw = zq.w - ze.w;
        s += dx * dx + dy * dy + dz * dz + dw * dw;
    }
#pragma unroll
    for (int o = 16; o > 0; o >>= 1) s += __shfl_down_sync(0xffffffffu, s, o);
    if (lane == 0) wsum[warp] = s;
    __syncthreads();
    if (threadIdx.x == 0) {
        float t = 0.f;
#pragma unroll
        for (int wv = 0; wv < 8; wv++) t += wsum[wv];
        g_losspart[blockIdx.x] = t;
    }
}

/* ---------- K3: deterministic final loss ---------- */
__global__ void loss_kernel(float* __restrict__ out) {
    __shared__ float s[256];
    float t = 0.f;
    for (int i = threadIdx.x; i < NPART; i += 256) t += g_losspart[i];
    s[threadIdx.x] = t;
    __syncthreads();
    for (int o = 128; o > 0; o >>= 1) {
        if (threadIdx.x < o) s[threadIdx.x] += s[threadIdx.x + o];
        __syncthreads();
    }
    if (threadIdx.x == 0)
        out[(size_t)NROWS * DIM] = 2.f * s[0] / (float)((size_t)NROWS * DIM);
}

extern "C" void kernel_launch(void* const* d_in, const int* in_sizes, int n_in,
                              void* d_out, int out_size) {
    const float* z  = (const float*)d_in[0];
    const float* cb = (const float*)d_in[1];
    float* out = (float*)d_out;

    cudaFuncSetAttribute(vq_mma_kernel, cudaFuncAttributeMaxDynamicSharedMemorySize, GEMM_SMEM);

    split_z_kernel<<<NROWS * 16 / 256, 256>>>(z);
    split_cb_kernel<<<KCB * 16 / 256, 256>>>(cb);
    codenorm_kernel<<<KCB / 8, 256>>>(cb);
    vq_mma_kernel<<<MTILES, 256, GEMM_SMEM>>>();
    rescore_gather_kernel<<<NROWS / 8, 256>>>(z, cb, out);
    loss_kernel<<<1, 256>>>(out);
}

// round 8
// speedup vs baseline: 1.2183x; 1.2183x over previous
#include <cuda_runtime.h>
#include <cuda_fp16.h>
#include <math_constants.h>
#include <cstdint>

#define NROWS 16384
#define DIM   256
#define KCB   8192
#define MT    64                 /* rows per CTA           */
#define MTILES (NROWS / MT)      /* 256 CTAs               */
#define NTILES (KCB / 128)       /* 64 code tiles          */
#define NHALF  (2 * NTILES)      /* 128 k128xn128 halves   */
#define NPART (NROWS / 8)

/* GEMM smem layout (dynamic) */
#define SA_OFF  0                /* A fp16: 4 sub-chunks x 8KB = 32768 */
#define SB_OFF  32768            /* 2 x 32KB B half double buffer      */
#define SCN_OFF 98304            /* 2 x 512B codenorm tiles            */
#define GEMM_SMEM 99328

/* ------------- device globals (no allocs allowed) ------------- */
__device__ unsigned char g_zt[MTILES * 32768];       /* 8MB pre-swizzled A fp16       */
__device__ unsigned char g_cbt[NHALF * 32768];       /* 4MB pre-swizzled B fp16 halves*/
__device__ float g_codenorm[KCB];
__device__ int   g_cand[NROWS * 4];
__device__ float g_losspart[NPART];
__device__ unsigned g_ctr;

/* ------------- helpers ------------- */
__device__ __forceinline__ unsigned smem_u32(const void* p) {
    unsigned a;
    asm("{ .reg .u64 t; cvta.to.shared.u64 t, %1; cvt.u32.u64 %0, t; }" : "=r"(a) : "l"(p));
    return a;
}
__device__ __forceinline__ void cp_async16(unsigned dst, const void* src) {
    asm volatile("cp.async.cg.shared.global [%0], [%1], 16;" :: "r"(dst), "l"(src) : "memory");
}
__device__ __forceinline__ void ldsm_x4(unsigned* r, unsigned addr) {
    asm("ldmatrix.sync.aligned.m8n8.x4.shared.b16 {%0,%1,%2,%3}, [%4];"
        : "=r"(r[0]), "=r"(r[1]), "=r"(r[2]), "=r"(r[3]) : "r"(addr));
}
__device__ __forceinline__ void ldsm_x4_t(unsigned* r, unsigned addr) {
    asm("ldmatrix.sync.aligned.m8n8.x4.trans.shared.b16 {%0,%1,%2,%3}, [%4];"
        : "=r"(r[0]), "=r"(r[1]), "=r"(r[2]), "=r"(r[3]) : "r"(addr));
}
__device__ __forceinline__ void mma16816(float (&c)[4], const unsigned* a, unsigned b0, unsigned b1) {
    asm volatile("mma.sync.aligned.m16n8k16.row.col.f32.f16.f16.f32 "
                 "{%0,%1,%2,%3}, {%4,%5,%6,%7}, {%8,%9}, {%0,%1,%2,%3};"
                 : "+f"(c[0]), "+f"(c[1]), "+f"(c[2]), "+f"(c[3])
                 : "r"(a[0]), "r"(a[1]), "r"(a[2]), "r"(a[3]), "r"(b0), "r"(b1));
}
__device__ __forceinline__ void top2_update(float& v1, int& i1, float& v2, int& i2, float d, int c) {
    if (d < v2) {
        if (d < v1) { v2 = v1; i2 = i1; v1 = d; i1 = c; }
        else        { v2 = d;  i2 = c; }
    }
}
__device__ __forceinline__ void ins4(float (&cv)[4], int (&ci)[4], float v, int i) {
#pragma unroll
    for (int j = 0; j < 4; j++) {
        bool lt = (v < cv[j]) || (v == cv[j] && i < ci[j]);
        float tv = lt ? cv[j] : v; int ti = lt ? ci[j] : i;
        if (lt) { cv[j] = v; ci[j] = i; }
        v = tv; i = ti;
    }
}

/* ---------- preprocess: z -> swizzled fp16 tiles (64 rows x 4 k64 sub-chunks) ---------- */
__global__ void split_z_kernel(const float* __restrict__ z) {
    const int id = blockIdx.x * 256 + threadIdx.x;
    const int row = id >> 5;
    const int j = id & 31;
    const float* src = z + (size_t)row * DIM + j * 8;
    float4 f0 = __ldg((const float4*)src);
    float4 f1 = __ldg((const float4*)(src + 4));
    float v[8] = {f0.x, f0.y, f0.z, f0.w, f1.x, f1.y, f1.z, f1.w};
    unsigned short hv[8];
#pragma unroll
    for (int e = 0; e < 8; e++) hv[e] = __half_as_ushort(__float2half_rn(v[e]));
    const int m = row & 63;
    const int kc = j >> 3, c = j & 7;
    size_t base = (size_t)(row >> 6) * 32768 + (size_t)kc * 8192 + m * 128 + ((c ^ (m & 7)) << 4);
    *(uint4*)(g_zt + base) = *(uint4*)hv;
}

/* ---------- preprocess: codebook -> k-major swizzled fp16 32KB halves ---------- */
__global__ void split_cb_kernel(const float* __restrict__ cb) {
    __shared__ __half sh[128][136];
    const int hidx = blockIdx.x;           /* 0..127 */
    const int nt = hidx >> 1, h = hidx & 1;
    const int tid = threadIdx.x;
    const int n = tid >> 1, khalf = (tid & 1) * 64;
    const float* src = cb + (size_t)(nt * 128 + n) * DIM + h * 128 + khalf;
#pragma unroll
    for (int j = 0; j < 16; j++) {
        float4 f = __ldg((const float4*)(src + j * 4));
        sh[khalf + j * 4 + 0][n] = __float2half_rn(f.x);
        sh[khalf + j * 4 + 1][n] = __float2half_rn(f.y);
        sh[khalf + j * 4 + 2][n] = __float2half_rn(f.z);
        sh[khalf + j * 4 + 3][n] = __float2half_rn(f.w);
    }
    __syncthreads();
    unsigned char* dst = g_cbt + (size_t)hidx * 32768;
#pragma unroll
    for (int j = 0; j < 8; j++) {
        int u = tid + j * 256;              /* 0..2047 */
        int k = u >> 4, c = u & 15;
        uint4 v = *(const uint4*)(&sh[k][c * 8]);
        *(uint4*)(dst + (size_t)k * 256 + ((c ^ (k & 7)) << 4)) = v;
    }
}

/* ---------- exact fp32 codebook norms ---------- */
__global__ void codenorm_kernel(const float* __restrict__ cb) {
    int warp = threadIdx.x >> 5, lane = threadIdx.x & 31;
    int row = blockIdx.x * 8 + warp;
    const float4* c4 = (const float4*)(cb + (size_t)row * DIM);
    float s = 0.f;
#pragma unroll
    for (int l = 0; l < 2; l++) {
        float4 v = c4[lane + 32 * l];
        s += v.x * v.x + v.y * v.y + v.z * v.z + v.w * v.w;
    }
#pragma unroll
    for (int o = 16; o > 0; o >>= 1) s += __shfl_down_sync(0xffffffffu, s, o);
    if (lane == 0) g_codenorm[row] = s;
}

/* ---------- B-half producer: 32KB into buffer (s&1), one commit group ---------- */
__device__ __forceinline__ void issue_half(unsigned smb, int s, int tid) {
    const unsigned char* src = g_cbt + (size_t)s * 32768 + tid * 16;
    unsigned dst = smb + SB_OFF + (s & 1) * 32768 + tid * 16;
#pragma unroll
    for (int i = 0; i < 8; i++) cp_async16(dst + i * 4096, src + (size_t)i * 4096);
    if ((s & 1) == 0 && tid < 32)
        cp_async16(smb + SCN_OFF + ((s >> 1) & 1) * 512 + tid * 16,
                   (const unsigned char*)g_codenorm + (size_t)(s >> 1) * 512 + tid * 16);
    asm volatile("cp.async.commit_group;" ::: "memory");
}

/* ---------- compute one k128 half: 8 k16-steps, 2-stage register pipeline ---------- */
template<int H>
__device__ __forceinline__ void compute_half(float (&acc)[2][4][4], unsigned smb,
                                             int wm, int wn, int lane) {
    const int mlo = wm * 32 + (lane & 15);
    const int mhi = mlo + 16;
    const int klane = lane & 15;
    const int sel = lane >> 4;
    const unsigned alo_base = smb + SA_OFF + mlo * 128;
    const unsigned ahi_base = smb + SA_OFF + mhi * 128;
    const int xlo = mlo & 7, xhi = mhi & 7;
    const int cb0 = wn * 4 + sel;
    const unsigned bb = smb + SB_OFF + H * 32768 + klane * 256;
    const unsigned b0base = bb + (((cb0)     ^ (klane & 7)) << 4);
    const unsigned b1base = bb + (((cb0 + 2) ^ (klane & 7)) << 4);

    unsigned a0[2][4], a1[2][4], b0[2][4], b1[2][4];
#define LOAD_KS(buf, KS) do {                                            \
        const int base_g = H * 16 + (KS) * 2;                            \
        const int sub = base_g >> 3;                                     \
        const int kc = (base_g & 7) + sel;                               \
        ldsm_x4(a0[buf], alo_base + sub * 8192 + ((kc ^ xlo) << 4));     \
        ldsm_x4(a1[buf], ahi_base + sub * 8192 + ((kc ^ xhi) << 4));     \
        ldsm_x4_t(b0[buf], b0base + (KS) * 4096);                        \
        ldsm_x4_t(b1[buf], b1base + (KS) * 4096);                        \
    } while (0)

    LOAD_KS(0, 0);
#pragma unroll
    for (int ks = 0; ks < 8; ks++) {
        const int cur = ks & 1;
        if (ks < 7) LOAD_KS(cur ^ 1, ks + 1);
        mma16816(acc[0][0], a0[cur], b0[cur][0], b0[cur][1]);
        mma16816(acc[0][1], a0[cur], b0[cur][2], b0[cur][3]);
        mma16816(acc[0][2], a0[cur], b1[cur][0], b1[cur][1]);
        mma16816(acc[0][3], a0[cur], b1[cur][2], b1[cur][3]);
        mma16816(acc[1][0], a1[cur], b0[cur][0], b0[cur][1]);
        mma16816(acc[1][1], a1[cur], b0[cur][2], b0[cur][3]);
        mma16816(acc[1][2], a1[cur], b1[cur][0], b1[cur][1]);
        mma16816(acc[1][3], a1[cur], b1[cur][2], b1[cur][3]);
    }
#undef LOAD_KS
}

/* ---------- K1: fp16 tensor GEMM + fused top-2/thread argmin ---------- */
__global__ void __launch_bounds__(256, 2) vq_mma_kernel() {
    extern __shared__ __align__(128) unsigned char smem[];
    const unsigned smb = smem_u32(smem);
    const int tid = threadIdx.x;
    const int lane = tid & 31;
    const int w = tid >> 5;
    const int wm = w >> 2, wn = w & 3;
    const int mtile = blockIdx.x;

    if (mtile == 0 && tid == 0) g_ctr = 0;   /* reset rescore completion counter */

    { /* prologue group: resident A (32KB) + half 0 + cn tile 0 */
        const unsigned char* src = g_zt + (size_t)mtile * 32768 + tid * 16;
        unsigned dst = smb + SA_OFF + tid * 16;
#pragma unroll
        for (int i = 0; i < 8; i++) cp_async16(dst + i * 4096, src + (size_t)i * 4096);
        issue_half(smb, 0, tid);   /* commits A + half0 + cn0 as one group */
    }

    float acc[2][4][4];
#pragma unroll
    for (int i = 0; i < 2; i++)
#pragma unroll
        for (int j = 0; j < 4; j++)
#pragma unroll
            for (int r = 0; r < 4; r++) acc[i][j][r] = 0.f;
    float tv1[4], tv2[4];
    int ti1[4], ti2[4];
#pragma unroll
    for (int sl = 0; sl < 4; sl++) { tv1[sl] = CUDART_INF_F; tv2[sl] = CUDART_INF_F; ti1[sl] = 0; ti2[sl] = 0; }

    const int colb = wn * 32 + 2 * (lane & 3);
    for (int ii = 0; ii < NTILES; ii++) {
        /* ---- half 0 of tile ii ---- */
        asm volatile("cp.async.wait_group 0;" ::: "memory");
        __syncthreads();
        issue_half(smb, 2 * ii + 1, tid);
        compute_half<0>(acc, smb, wm, wn, lane);
        /* ---- half 1 of tile ii ---- */
        asm volatile("cp.async.wait_group 0;" ::: "memory");
        __syncthreads();
        if (2 * ii + 2 < NHALF) issue_half(smb, 2 * ii + 2, tid);
        compute_half<1>(acc, smb, wm, wn, lane);
        { /* epilogue: dist + top-2, zero acc */
            const float* cnp = (const float*)(smem + SCN_OFF + (ii & 1) * 512);
#pragma unroll
            for (int ni = 0; ni < 4; ni++) {
                float cn0 = cnp[colb + ni * 8];
                float cn1 = cnp[colb + ni * 8 + 1];
                int c0 = ii * 128 + colb + ni * 8;
#pragma unroll
                for (int mi = 0; mi < 2; mi++) {
#pragma unroll
                    for (int h = 0; h < 2; h++) {
                        int sl = mi * 2 + h;
                        float d0 = fmaf(-2.f, acc[mi][ni][h * 2],     cn0);
                        float d1 = fmaf(-2.f, acc[mi][ni][h * 2 + 1], cn1);
                        top2_update(tv1[sl], ti1[sl], tv2[sl], ti2[sl], d0, c0);
                        top2_update(tv1[sl], ti1[sl], tv2[sl], ti2[sl], d1, c0 + 1);
                        acc[mi][ni][h * 2] = 0.f;
                        acc[mi][ni][h * 2 + 1] = 0.f;
                    }
                }
            }
        }
    }

    /* dump all 32 per-row candidates, then per-row top-4 merge */
    __syncthreads();
    float4* red = (float4*)(smem + SB_OFF);    /* 64 rows x 16 entries x 16B */
#pragma unroll
    for (int sl = 0; sl < 4; sl++) {
        int row = wm * 32 + (sl >> 1) * 16 + (sl & 1) * 8 + (lane >> 2);
        red[row * 16 + wn * 4 + (lane & 3)] =
            make_float4(tv1[sl], __int_as_float(ti1[sl]), tv2[sl], __int_as_float(ti2[sl]));
    }
    __syncthreads();
    if (tid < 64) {
        float cv[4] = {CUDART_INF_F, CUDART_INF_F, CUDART_INF_F, CUDART_INF_F};
        int ci[4] = {0x7fffffff, 0x7fffffff, 0x7fffffff, 0x7fffffff};
#pragma unroll
        for (int e = 0; e < 16; e++) {
            float4 f = red[tid * 16 + e];
            ins4(cv, ci, f.x, __float_as_int(f.y));
            ins4(cv, ci, f.z, __float_as_int(f.w));
        }
        *(int4*)(g_cand + (size_t)(mtile * MT + tid) * 4) = make_int4(ci[0], ci[1], ci[2], ci[3]);
    }
}

/* ---------- K2: exact fp32 rescore of top-4 + gather + loss (last block finalizes) ---------- */
__global__ void rescore_gather_kernel(const float* __restrict__ z,
                                      const float* __restrict__ cb,
                                      float* __restrict__ out) {
    const int lane = threadIdx.x & 31, warp = threadIdx.x >> 5;
    const int row = blockIdx.x * 8 + warp;
    __shared__ float wsum[8];
    __shared__ float sred[256];
    __shared__ int s_last;

    const int4 cc = *(const int4*)(g_cand + (size_t)row * 4);
    const int cand[4] = {cc.x, cc.y, cc.z, cc.w};
    const float4* z4 = (const float4*)(z + (size_t)row * DIM);
    float4 a[2], b[4][2];
    float d[4] = {0.f, 0.f, 0.f, 0.f};
#pragma unroll
    for (int l = 0; l < 2; l++) {
        int f = lane + 32 * l;
        a[l] = z4[f];
#pragma unroll
        for (int q = 0; q < 4; q++) {
            b[q][l] = ((const float4*)(cb + (size_t)cand[q] * DIM))[f];
            d[q] += a[l].x * b[q][l].x + a[l].y * b[q][l].y
                  + a[l].z * b[q][l].z + a[l].w * b[q][l].w;
        }
    }
#pragma unroll
    for (int o = 16; o > 0; o >>= 1)
#pragma unroll
        for (int q = 0; q < 4; q++) d[q] += __shfl_xor_sync(0xffffffffu, d[q], o);

    float bv = CUDART_INF_F; int bq = 0, bi = 0x7fffffff;
#pragma unroll
    for (int q = 0; q < 4; q++) {
        float dist = fmaf(-2.f, d[q], __ldg(&g_codenorm[cand[q]]));
        if (dist < bv || (dist == bv && cand[q] < bi)) { bv = dist; bi = cand[q]; bq = q; }
    }

    float* out_ze = out + (size_t)row * DIM;
    float* out_zq = out + (size_t)NROWS * DIM + 1 + (size_t)row * DIM;
    float s = 0.f;
#pragma unroll
    for (int l = 0; l < 2; l++) {
        int f = lane + 32 * l;
        float4 ze = a[l];
        float4 zq = b[bq][l];
        *(float4*)(out_ze + f * 4) = ze;
        out_zq[f * 4 + 0] = zq.x; out_zq[f * 4 + 1] = zq.y;
        out_zq[f * 4 + 2] = zq.z; out_zq[f * 4 + 3] = zq.w;
        float dx = zq.x - ze.x, dy = zq.y - ze.y, dz = zq.z - ze.z, dw = zq.w - ze.w;
        s += dx * dx + dy * dy + dz * dz + dw * dw;
    }
#pragma unroll
    for (int o = 16; o > 0; o >>= 1) s += __shfl_down_sync(0xffffffffu, s, o);
    if (lane == 0) wsum[warp] = s;
    __syncthreads();
    if (threadIdx.x == 0) {
        float t = 0.f;
#pragma unroll
        for (int wv = 0; wv < 8; wv++) t += wsum[wv];
        g_losspart[blockIdx.x] = t;
        __threadfence();
        unsigned r = atomicAdd(&g_ctr, 1u);
        s_last = (r == NPART - 1) ? 1 : 0;
    }
    __syncthreads();
    if (s_last) {  /* last block: deterministic fixed-order final reduce */
        float t = 0.f;
        for (int i = threadIdx.x; i < NPART; i += 256) t += g_losspart[i];
        sred[threadIdx.x] = t;
        __syncthreads();
        for (int o = 128; o > 0; o >>= 1) {
            if (threadIdx.x < o) sred[threadIdx.x] += sred[threadIdx.x + o];
            __syncthreads();
        }
        if (threadIdx.x == 0)
            out[(size_t)NROWS * DIM] = 2.f * sred[0] / (float)((size_t)NROWS * DIM);
    }
}

extern "C" void kernel_launch(void* const* d_in, const int* in_sizes, int n_in,
                              void* d_out, int out_size) {
    const float* z  = (const float*)d_in[0];
    const float* cb = (const float*)d_in[1];
    float* out = (float*)d_out;

    cudaFuncSetAttribute(vq_mma_kernel, cudaFuncAttributeMaxDynamicSharedMemorySize, GEMM_SMEM);

    split_z_kernel<<<NROWS * 32 / 256, 256>>>(z);
    split_cb_kernel<<<NHALF, 256>>>(cb);
    codenorm_kernel<<<KCB / 8, 256>>>(cb);
    vq_mma_kernel<<<MTILES, 256, GEMM_SMEM>>>();
    rescore_gather_kernel<<<NPART, 256>>>(z, cb, out);
}